// round 3
// baseline (speedup 1.0000x reference)
#include <cuda_runtime.h>
#include <stdint.h>

// DynamicConvolution: out[b,co,y,x] = sum_{ci,ky,kx} feat[b,ci,y+ky-1,x+kx-1] * w[b,co,ci,ky,kx]
// B=16, Cin=Cout=128, H=W=64, K=3, pad=1, fp32.
//
// Strategy: direct conv, block = (batch b, 32 couts, 8 rows x 64 cols).
// cin processed in chunks of 4 through shared memory.
// Math uses packed fp32x2 FFMA (fma.rn.f32x2) over cout-PAIRS:
//   - weight pairs come directly from LDS.128 (adjacent couts contiguous in smem)
//   - input scalar duplicated into both halves with one mov.b64
// Each thread: 8 couts (4 pairs) x 8 pixels = 32 packed accumulators (64 regs).

#define BATCH   16
#define CIN     128
#define COUT    128
#define HH      64
#define WW      64
#define CC      4       // cin chunk
#define CTILE   32      // couts per block
#define RTILE   8       // output rows per block
#define ISTRIDE 67      // smem input row stride (67 mod 32 = 3 -> minimal conflicts)
#define NTHREADS 256

__device__ __forceinline__ unsigned long long dup_f32(float v) {
    unsigned long long r;
    unsigned int u = __float_as_uint(v);
    asm("mov.b64 %0, {%1, %1};" : "=l"(r) : "r"(u));
    return r;
}

__device__ __forceinline__ void ffma2(unsigned long long& acc,
                                      unsigned long long a,
                                      unsigned long long b) {
    asm("fma.rn.f32x2 %0, %1, %2, %0;" : "+l"(acc) : "l"(a), "l"(b));
}

__global__ void __launch_bounds__(NTHREADS, 2)
dynconv_kernel(const float* __restrict__ feat,
               const float* __restrict__ wt,
               float* __restrict__ out)
{
    // input tile: CC cins x 10 rows (8 + halo) x 66 cols (64 + halo), stride 67
    __shared__ __align__(16) float in_s[CC * 10 * ISTRIDE];
    // weights: [cin*9 + tap][32 couts] -> compute reads are vectorized + broadcast
    __shared__ __align__(16) float w_s[CC * 9 * CTILE];

    const int b     = blockIdx.z;
    const int cout0 = blockIdx.y * CTILE;
    const int row0  = blockIdx.x * RTILE;

    const int tid  = threadIdx.x;
    const int cg   = tid >> 6;        // cout subgroup (8 couts) -- constant within a warp
    const int p    = tid & 63;        // pixel group
    const int prow = p >> 3;          // 0..7: row within tile
    const int x0   = (p & 7) << 3;    // 0..56: col base (8 consecutive pixels)

    unsigned long long acc[4][8];
    #pragma unroll
    for (int i = 0; i < 4; i++)
        #pragma unroll
        for (int j = 0; j < 8; j++) acc[i][j] = 0ull;

    const float* featb = feat + (long)b * CIN * (HH * WW);
    const float* wtb   = wt   + ((long)b * COUT + cout0) * (CIN * 9);

    for (int cin0 = 0; cin0 < CIN; cin0 += CC) {
        __syncthreads();

        // ---- fill weights: co = idx&31 -> conflict-free STS; global reads hit L2
        for (int idx = tid; idx < CTILE * CC * 9; idx += NTHREADS) {
            int co = idx & 31;
            int t  = idx >> 5;                    // 0..35 = cin_local*9 + tap
            w_s[t * 32 + co] = wtb[(long)co * (CIN * 9) + cin0 * 9 + t];
        }

        // ---- fill input tile with zero-padded halo (rows row0-1..row0+8, cols -1..64)
        for (int idx = tid; idx < CC * 10 * 66; idx += NTHREADS) {
            int cin = idx / 660;
            int rem = idx - cin * 660;
            int r   = rem / 66;
            int col = rem - r * 66;
            int y = row0 + r - 1;
            int x = col - 1;
            float v = 0.f;
            if ((unsigned)y < HH && (unsigned)x < WW)
                v = featb[(long)(cin0 + cin) * (HH * WW) + y * WW + x];
            in_s[cin * (10 * ISTRIDE) + r * ISTRIDE + col] = v;
        }
        __syncthreads();

        // ---- compute
        #pragma unroll
        for (int cin = 0; cin < CC; cin++) {
            #pragma unroll
            for (int ky = 0; ky < 3; ky++) {
                // window: smem cols x0 .. x0+9  (input x = x0+j-1)
                const float* wrow =
                    &in_s[cin * (10 * ISTRIDE) + (prow + ky) * ISTRIDE + x0];
                unsigned long long d[10];
                #pragma unroll
                for (int j = 0; j < 10; j++) d[j] = dup_f32(wrow[j]);

                #pragma unroll
                for (int kx = 0; kx < 3; kx++) {
                    const float* wp = &w_s[(cin * 9 + ky * 3 + kx) * 32 + cg * 8];
                    ulonglong2 wv0 = *(const ulonglong2*)(wp);      // couts +0,+1 / +2,+3
                    ulonglong2 wv1 = *(const ulonglong2*)(wp + 4);  // couts +4,+5 / +6,+7
                    #pragma unroll
                    for (int px = 0; px < 8; px++) {
                        ffma2(acc[0][px], wv0.x, d[px + kx]);
                        ffma2(acc[1][px], wv0.y, d[px + kx]);
                        ffma2(acc[2][px], wv1.x, d[px + kx]);
                        ffma2(acc[3][px], wv1.y, d[px + kx]);
                    }
                }
            }
        }
    }

    // ---- writeout: acc[k][px] = couts (cg*8 + 2k, cg*8 + 2k + 1), pixel (row0+prow, x0+px)
    const int y = row0 + prow;
    float* outb = out + ((long)b * COUT + cout0 + cg * 8) * (HH * WW) + y * WW + x0;
    #pragma unroll
    for (int k = 0; k < 4; k++) {
        #pragma unroll
        for (int px = 0; px < 8; px++) {
            unsigned int ulo, uhi;
            asm("mov.b64 {%0, %1}, %2;" : "=r"(ulo), "=r"(uhi) : "l"(acc[k][px]));
            outb[(long)(2 * k)     * (HH * WW) + px] = __uint_as_float(ulo);
            outb[(long)(2 * k + 1) * (HH * WW) + px] = __uint_as_float(uhi);
        }
    }
}

extern "C" void kernel_launch(void* const* d_in, const int* in_sizes, int n_in,
                              void* d_out, int out_size)
{
    const float* feat = (const float*)d_in[0];   // (16,128,64,64)
    const float* wt   = (const float*)d_in[1];   // (16,128,128,3,3)
    float* out        = (float*)d_out;           // (16,128,64,64)
    (void)in_sizes; (void)n_in; (void)out_size;

    dim3 grid(HH / RTILE, COUT / CTILE, BATCH);  // (8, 4, 16) = 512 blocks
    dynconv_kernel<<<grid, NTHREADS>>>(feat, wt, out);
}

// round 8
// speedup vs baseline: 1.7260x; 1.7260x over previous
#include <cuda_runtime.h>
#include <cuda_bf16.h>
#include <stdint.h>

// DynamicConvolution via warp-level bf16 mma.sync (HMMA) with 2-term fp32 emulation.
// (tcgen05 is unavailable: harness PTX targets sm_103 without the 'a' feature set.)
//
// out[b,co,y,x] = sum_{ci,ky,kx} feat[b,ci,y+ky-1,x+kx-1] * w[b,co,ci,ky,kx]
// B=16, Cin=Cout=128, H=W=64, K=3, pad=1, fp32.
//
// Pass 1 (fsplit): feat -> zero-padded transposed bf16 hi/lo  fT[b][yp:66][xp:66][ci:128]
// Pass 2 (wsplit): w    -> bf16 hi/lo                         wT[b][tap:9][co:128][ci:128]
// Pass 3 (main):   CTA = (b, 2 output rows). D[128co x 128px] in registers,
//                  accumulated over 9 taps x K=128 x {hh,hl,lh} split combos.
//                  B (feature) tile persistent in smem; A (weights) reloaded per tap.

#define BATCH 16
#define CIN   128
#define COUT  128
#define HH    64
#define WW    64
#define PADW  66

__device__ __nv_bfloat16 g_fhi[(size_t)BATCH * PADW * PADW * CIN];
__device__ __nv_bfloat16 g_flo[(size_t)BATCH * PADW * PADW * CIN];
__device__ __nv_bfloat16 g_whi[(size_t)BATCH * 9 * COUT * CIN];
__device__ __nv_bfloat16 g_wlo[(size_t)BATCH * 9 * COUT * CIN];

// ============================ split kernels ============================

__global__ void fsplit_kernel(const float* __restrict__ feat)
{
    __shared__ float s[64 * 129];   // [x][ci], pad 129 to kill bank conflicts
    const int b  = blockIdx.y;
    const int yp = blockIdx.x;      // 0..65
    const int tid = threadIdx.x;
    const bool interior = (yp >= 1 && yp <= 64);

    if (interior) {
        const int y = yp - 1;
        const float* src = feat + (size_t)b * CIN * (HH * WW) + y * WW;
        for (int i = tid; i < CIN * WW; i += 256) {
            int ci = i >> 6, x = i & 63;
            s[x * 129 + ci] = src[(size_t)ci * (HH * WW) + x];
        }
    }
    __syncthreads();

    const size_t ob = ((size_t)b * PADW + yp) * PADW * CIN;
    for (int i = tid; i < PADW * CIN; i += 256) {
        int xp = i >> 7, ci = i & 127;
        float v = 0.f;
        if (interior && xp >= 1 && xp <= 64) v = s[(xp - 1) * 129 + ci];
        __nv_bfloat16 h = __float2bfloat16(v);
        __nv_bfloat16 l = __float2bfloat16(v - __bfloat162float(h));
        g_fhi[ob + i] = h;
        g_flo[ob + i] = l;
    }
}

__global__ void wsplit_kernel(const float* __restrict__ wt)
{
    size_t i = (size_t)blockIdx.x * 256 + threadIdx.x;   // over 16*128*128
    if (i >= (size_t)BATCH * COUT * CIN) return;
    int ci = (int)(i & 127);
    int co = (int)((i >> 7) & 127);
    int b  = (int)(i >> 14);
    const float* src = wt + (((size_t)b * COUT + co) * CIN + ci) * 9;
    #pragma unroll
    for (int tap = 0; tap < 9; tap++) {
        float v = src[tap];
        __nv_bfloat16 h = __float2bfloat16(v);
        __nv_bfloat16 l = __float2bfloat16(v - __bfloat162float(h));
        size_t o = (((size_t)b * 9 + tap) * COUT + co) * CIN + ci;
        g_whi[o] = h;
        g_wlo[o] = l;
    }
}

// ============================ PTX helpers ============================

__device__ __forceinline__ uint32_t smem_u32(const void* p) {
    uint32_t a;
    asm("{ .reg .u64 t; cvta.to.shared.u64 t, %1; cvt.u32.u64 %0, t; }"
        : "=r"(a) : "l"(p));
    return a;
}

#define LDSM4(r, addr)                                                        \
    asm volatile("ldmatrix.sync.aligned.m8n8.x4.shared.b16 {%0,%1,%2,%3}, [%4];" \
        : "=r"((r)[0]), "=r"((r)[1]), "=r"((r)[2]), "=r"((r)[3]) : "r"(addr))

#define MMA16816(c, a, b0, b1)                                                \
    asm volatile("mma.sync.aligned.m16n8k16.row.col.f32.bf16.bf16.f32 "       \
        "{%0,%1,%2,%3}, {%4,%5,%6,%7}, {%8,%9}, {%0,%1,%2,%3};"               \
        : "+f"((c)[0]), "+f"((c)[1]), "+f"((c)[2]), "+f"((c)[3])              \
        : "r"((a)[0]), "r"((a)[1]), "r"((a)[2]), "r"((a)[3]),                 \
          "r"(b0), "r"(b1))

// ============================ main kernel ============================

// SMEM (dynamic, bytes):
//   B persistent: [split:2][row:4][col:66][ci:128 pad->136]  2*71808 = 143616
//   A per tap:    [split:2][co:128][ci:128 pad->136]         2*34816 =  69632
#define B_OFF      0
#define B_SPLIT    71808           // 4*66*272
#define A_OFF      143616
#define A_SPLIT    34816           // 128*272
#define ROWB       272             // 136 bf16 per row (128 + 8 pad) -> conflict-free LDSM
#define SMEM_TOTAL 213248

__global__ void __launch_bounds__(256, 1)
dynconv_mma_kernel(float* __restrict__ out)
{
    extern __shared__ char smem[];
    const uint32_t sa = smem_u32(smem);
    const int tid = threadIdx.x;
    const int wid = tid >> 5;
    const int l   = tid & 31;
    const int b   = blockIdx.y;
    const int y0  = blockIdx.x * 2;        // two output rows per CTA

    // warp tile: 64 (M=couts) x 32 (N=pixels); warps: mw in {0,1}, nw in {0..3}
    const int mw = wid & 1;
    const int nw = wid >> 1;
    const int M0 = mw * 64;
    const int pr = nw >> 1;                // pixel row within CTA (0/1)
    const int pc = (nw & 1) * 32;          // pixel col base

    const __nv_bfloat16* fbase[2] = { g_fhi + (size_t)b * PADW * PADW * CIN,
                                      g_flo + (size_t)b * PADW * PADW * CIN };

    // ---- fill persistent B tile: rows y0..y0+3 (padded), all 66 cols, hi/lo ----
    #pragma unroll
    for (int s = 0; s < 2; s++) {
        const __nv_bfloat16* fb = fbase[s];
        for (int i = tid; i < 4224; i += 256) {          // 4*66*16 uint4 chunks
            int q  = i & 15;
            int rc = i >> 4;                              // 0..263
            int r  = rc / 66;
            int c  = rc - r * 66;
            uint4 v = *(const uint4*)(fb + ((size_t)(y0 + r) * PADW + c) * CIN + q * 8);
            *(uint4*)(smem + B_OFF + s * B_SPLIT + (r * 66 + c) * ROWB + q * 16) = v;
        }
    }

    // ---- ldmatrix lane address components ----
    // A (x4 over m16 x k16): row = m_base + (l&15), k-col = 8*(l>>4)
    const uint32_t aBase = sa + A_OFF + (uint32_t)(M0 + (l & 15)) * ROWB
                         + (uint32_t)((l >> 4) << 3) * 2;
    // B (x4 over n16 x k16): n = n_base + (l&7) + 8*(l>>4), k-half = (l>>3)&1
    const int n_l   = (l & 7) + ((l >> 4) << 3);
    const int khalf = (l >> 3) & 1;

    float acc[4][4][4];
    #pragma unroll
    for (int i = 0; i < 4; i++)
        #pragma unroll
        for (int j = 0; j < 4; j++)
            #pragma unroll
            for (int k = 0; k < 4; k++) acc[i][j][k] = 0.f;

    for (int tap = 0; tap < 9; tap++) {
        const int ty = tap / 3, tx = tap % 3;

        __syncthreads();   // previous tap's A reads done (covers B fill at tap 0)

        // ---- load A tiles [128 co][128 ci] hi/lo for this tap ----
        #pragma unroll
        for (int s = 0; s < 2; s++) {
            const __nv_bfloat16* wb = (s ? g_wlo : g_whi)
                                    + ((size_t)(b * 9 + tap) * COUT) * CIN;
            #pragma unroll
            for (int it = 0; it < 8; it++) {
                int i = tid + it * 256;                   // 0..2047
                int co = i >> 4, q = i & 15;
                uint4 v = *(const uint4*)(wb + (size_t)co * CIN + q * 8);
                *(uint4*)(smem + A_OFF + s * A_SPLIT + co * ROWB + q * 16) = v;
            }
        }
        __syncthreads();

        const uint32_t bBase = sa + B_OFF
            + (uint32_t)(((pr + ty) * 66 + pc + tx + n_l)) * ROWB
            + (uint32_t)khalf * 16;

        // ---- compute: K=128 in 8 k16-steps, 3 split combos ----
        #pragma unroll
        for (int ks = 0; ks < 8; ks++) {
            uint32_t ah[4][4], al[4][4], bh[2][4], bl[2][4];
            #pragma unroll
            for (int tm = 0; tm < 4; tm++) {
                LDSM4(ah[tm], aBase + tm * (16 * ROWB) + ks * 32);
                LDSM4(al[tm], aBase + A_SPLIT + tm * (16 * ROWB) + ks * 32);
            }
            #pragma unroll
            for (int t = 0; t < 2; t++) {
                LDSM4(bh[t], bBase + t * (16 * ROWB) + ks * 32);
                LDSM4(bl[t], bBase + B_SPLIT + t * (16 * ROWB) + ks * 32);
            }
            #pragma unroll
            for (int tm = 0; tm < 4; tm++)
                #pragma unroll
                for (int tn = 0; tn < 4; tn++) {
                    float* c = acc[tm][tn];
                    uint32_t b0h = bh[tn >> 1][(tn & 1) * 2];
                    uint32_t b1h = bh[tn >> 1][(tn & 1) * 2 + 1];
                    uint32_t b0l = bl[tn >> 1][(tn & 1) * 2];
                    uint32_t b1l = bl[tn >> 1][(tn & 1) * 2 + 1];
                    MMA16816(c, ah[tm], b0h, b1h);   // hh
                    MMA16816(c, ah[tm], b0l, b1l);   // hl
                    MMA16816(c, al[tm], b0h, b1h);   // lh
                }
        }
    }

    // ---- epilogue: fragment -> out[b][co][y][x] ----
    // fragment: c0,c1 at (m = tm*16 + l/4, n = tn*8 + 2*(l%4)); c2,c3 at m+8
    const int g  = l >> 2;
    const int nc = 2 * (l & 3);
    #pragma unroll
    for (int tm = 0; tm < 4; tm++) {
        #pragma unroll
        for (int tn = 0; tn < 4; tn++) {
            int p = (nw * 32) + tn * 8 + nc;          // pixel index in CTA (0..127)
            int y = y0 + (p >> 6);
            int x = p & 63;
            int co = M0 + tm * 16 + g;
            float* o0 = out + (((size_t)b * COUT + co) * HH + y) * WW + x;
            *(float2*)o0 = make_float2(acc[tm][tn][0], acc[tm][tn][1]);
            float* o1 = o0 + 8 * (size_t)(HH * WW);   // co + 8
            *(float2*)o1 = make_float2(acc[tm][tn][2], acc[tm][tn][3]);
        }
    }
}

// ============================ launch ============================

extern "C" void kernel_launch(void* const* d_in, const int* in_sizes, int n_in,
                              void* d_out, int out_size)
{
    const float* feat = (const float*)d_in[0];   // (16,128,64,64)
    const float* wt   = (const float*)d_in[1];   // (16,128,128,3,3)
    float* out        = (float*)d_out;           // (16,128,64,64)
    (void)in_sizes; (void)n_in; (void)out_size;

    cudaFuncSetAttribute(dynconv_mma_kernel,
                         cudaFuncAttributeMaxDynamicSharedMemorySize, SMEM_TOTAL);

    fsplit_kernel<<<dim3(PADW, BATCH), 256>>>(feat);
    wsplit_kernel<<<(BATCH * COUT * CIN + 255) / 256, 256>>>(wt);
    dynconv_mma_kernel<<<dim3(HH / 2, BATCH), 256, SMEM_TOTAL>>>(out);
}

// round 10
// speedup vs baseline: 3.6304x; 2.1034x over previous
#include <cuda_runtime.h>
#include <cuda_fp16.h>
#include <stdint.h>

// DynamicConvolution via warp-level f16 mma.sync (HMMA), fp32-emulated with a
// 2-combo scheme: features split exactly into f16 hi+lo, weights rounded to f16.
//   out = sum (fh+fl) * w_f16   (error ~2^-11 from weight rounding only)
// B=16, Cin=Cout=128, H=W=64, K=3, pad=1, fp32.
//
// Pass 1 (fsplit): feat -> zero-padded transposed f16 hi/lo fT[b][yp:66][xp:66][ci:128]
// Pass 2 (wsplit): w    -> f16 (rounded)                    wT[b][tap:9][co:128][ci:128]
// Pass 3 (main):   CTA = (b, 2 output rows). D[128co x 128px] in registers,
//                  9 taps x K=128 x {h,l} combos. Feature tile persistent in smem;
//                  weight tile cp.async double-buffered per tap.

#define BATCH 16
#define CIN   128
#define COUT  128
#define HH    64
#define WW    64
#define PADW  66

__device__ __half g_fhi[(size_t)BATCH * PADW * PADW * CIN];
__device__ __half g_flo[(size_t)BATCH * PADW * PADW * CIN];
__device__ __half g_w16[(size_t)BATCH * 9 * COUT * CIN];

// ============================ split kernels ============================

__global__ void __launch_bounds__(512)
fsplit_kernel(const float* __restrict__ feat)
{
    __shared__ float s[64 * 129];   // [x][ci], pad 129 to kill bank conflicts
    const int b  = blockIdx.y;
    const int yp = blockIdx.x;      // 0..65
    const int tid = threadIdx.x;
    const bool interior = (yp >= 1 && yp <= 64);

    if (interior) {
        const int y = yp - 1;
        const float* src = feat + (size_t)b * CIN * (HH * WW) + y * WW;
        for (int i = tid; i < CIN * WW; i += 512) {
            int ci = i >> 6, x = i & 63;
            s[x * 129 + ci] = src[(size_t)ci * (HH * WW) + x];
        }
    }
    __syncthreads();

    const size_t ob = ((size_t)b * PADW + yp) * PADW * CIN;
    for (int i = tid; i < PADW * CIN; i += 512) {
        int xp = i >> 7, ci = i & 127;
        float v = 0.f;
        if (interior && xp >= 1 && xp <= 64) v = s[(xp - 1) * 129 + ci];
        __half h = __float2half(v);
        __half l = __float2half(v - __half2float(h));
        g_fhi[ob + i] = h;
        g_flo[ob + i] = l;
    }
}

__global__ void wsplit_kernel(const float* __restrict__ wt)
{
    size_t i = (size_t)blockIdx.x * 256 + threadIdx.x;   // over 16*128*128
    if (i >= (size_t)BATCH * COUT * CIN) return;
    int ci = (int)(i & 127);
    int co = (int)((i >> 7) & 127);
    int b  = (int)(i >> 14);
    const float* src = wt + (((size_t)b * COUT + co) * CIN + ci) * 9;
    #pragma unroll
    for (int tap = 0; tap < 9; tap++) {
        size_t o = (((size_t)b * 9 + tap) * COUT + co) * CIN + ci;
        g_w16[o] = __float2half(src[tap]);
    }
}

// ============================ PTX helpers ============================

__device__ __forceinline__ uint32_t smem_u32(const void* p) {
    uint32_t a;
    asm("{ .reg .u64 t; cvta.to.shared.u64 t, %1; cvt.u32.u64 %0, t; }"
        : "=r"(a) : "l"(p));
    return a;
}

__device__ __forceinline__ void cp16(uint32_t dst, const void* src) {
    asm volatile("cp.async.cg.shared.global [%0], [%1], 16;"
                 :: "r"(dst), "l"(src) : "memory");
}
#define CP_COMMIT() asm volatile("cp.async.commit_group;" ::: "memory")
#define CP_WAIT0()  asm volatile("cp.async.wait_group 0;" ::: "memory")

#define LDSM4(r, addr)                                                        \
    asm volatile("ldmatrix.sync.aligned.m8n8.x4.shared.b16 {%0,%1,%2,%3}, [%4];" \
        : "=r"((r)[0]), "=r"((r)[1]), "=r"((r)[2]), "=r"((r)[3]) : "r"(addr))

#define MMA16816(c, a, b0, b1)                                                \
    asm volatile("mma.sync.aligned.m16n8k16.row.col.f32.f16.f16.f32 "         \
        "{%0,%1,%2,%3}, {%4,%5,%6,%7}, {%8,%9}, {%0,%1,%2,%3};"               \
        : "+f"((c)[0]), "+f"((c)[1]), "+f"((c)[2]), "+f"((c)[3])              \
        : "r"((a)[0]), "r"((a)[1]), "r"((a)[2]), "r"((a)[3]),                 \
          "r"(b0), "r"(b1))

// ============================ main kernel ============================

// SMEM (dynamic, bytes):
//   F persistent: [split:2][row:4][col:66][ci:128 pad->136] f16  2*71808 = 143616
//   W per tap:    [buf:2][co:128][ci:128 pad->136] f16           2*34816 =  69632
#define F_OFF      0
#define F_SPLIT    71808           // 4*66*272
#define A_OFF      143616
#define A_BUF      34816           // 128*272
#define ROWB       272             // 136 f16 per row (128 + 8 pad) -> conflict-free LDSM
#define SMEM_TOTAL 213248

__global__ void __launch_bounds__(256, 1)
dynconv_mma_kernel(float* __restrict__ out)
{
    extern __shared__ char smem[];
    const uint32_t sa = smem_u32(smem);
    const int tid = threadIdx.x;
    const int wid = tid >> 5;
    const int l   = tid & 31;
    const int b   = blockIdx.y;
    const int y0  = blockIdx.x * 2;        // two output rows per CTA

    // warp tile: 64 (M=couts) x 32 (N=pixels); warps: mw in {0,1}, nw in {0..3}
    const int mw = wid & 1;
    const int nw = wid >> 1;
    const int M0 = mw * 64;
    const int pr = nw >> 1;                // pixel row within CTA (0/1)
    const int pc = (nw & 1) * 32;          // pixel col base

    // ---- prologue: cp.async fill of persistent F tile (both planes) ----
    {
        const __half* fh = g_fhi + (size_t)b * PADW * PADW * CIN;
        const __half* fl = g_flo + (size_t)b * PADW * PADW * CIN;
        #pragma unroll
        for (int it = 0; it < 33; it++) {              // 2*264*16 / 256
            int i = tid + it * 256;                    // 0..8447
            int plane = (i >= 4224);
            int j = i - plane * 4224;
            int rc = j >> 4;                           // 0..263 = r*66+c
            int q  = j & 15;
            int r  = rc / 66;
            int c  = rc - r * 66;
            const __half* src = (plane ? fl : fh)
                              + ((size_t)(y0 + r) * PADW + c) * CIN + q * 8;
            cp16(sa + F_OFF + plane * F_SPLIT + rc * ROWB + q * 16, src);
        }
        // W tap 0 into buffer 0
        const __half* wb = g_w16 + ((size_t)(b * 9 + 0) * COUT) * CIN;
        #pragma unroll
        for (int it = 0; it < 8; it++) {
            int i = tid + it * 256;
            int co = i >> 4, q = i & 15;
            cp16(sa + A_OFF + co * ROWB + q * 16, wb + (size_t)co * CIN + q * 8);
        }
        CP_COMMIT();
    }

    // ---- ldmatrix lane address components ----
    const uint32_t aLane = (uint32_t)((M0 + (l & 15)) * ROWB + (((l >> 4) << 3) << 1));
    const int n_l   = (l & 7) + ((l >> 4) << 3);
    const int khalf = (l >> 3) & 1;

    float acc[4][4][4];
    #pragma unroll
    for (int i = 0; i < 4; i++)
        #pragma unroll
        for (int j = 0; j < 4; j++)
            #pragma unroll
            for (int k = 0; k < 4; k++) acc[i][j][k] = 0.f;

    for (int tap = 0; tap < 9; tap++) {
        const int ty = tap / 3, tx = tap % 3;
        const int buf = tap & 1;

        CP_WAIT0();           // W[tap] (+F on tap 0) landed
        __syncthreads();      // all warps past tap-1 compute (frees buf^1)

        if (tap < 8) {        // prefetch W[tap+1] into the other buffer
            const __half* wb = g_w16 + ((size_t)(b * 9 + tap + 1) * COUT) * CIN;
            const uint32_t dst = sa + A_OFF + (buf ^ 1) * A_BUF;
            #pragma unroll
            for (int it = 0; it < 8; it++) {
                int i = tid + it * 256;
                int co = i >> 4, q = i & 15;
                cp16(dst + co * ROWB + q * 16, wb + (size_t)co * CIN + q * 8);
            }
            CP_COMMIT();
        }

        const uint32_t aBase = sa + A_OFF + buf * A_BUF + aLane;
        const uint32_t bBase = sa + F_OFF
            + (uint32_t)(((pr + ty) * 66 + pc + tx + n_l)) * ROWB
            + (uint32_t)khalf * 16;

        // ---- compute: K=128 in 8 k16-steps, 2 combos (w*fh, w*fl) ----
        #pragma unroll
        for (int ks = 0; ks < 8; ks++) {
            uint32_t w[4][4], bh[2][4], bl[2][4];
            #pragma unroll
            for (int tm = 0; tm < 4; tm++)
                LDSM4(w[tm], aBase + tm * (16 * ROWB) + ks * 32);
            #pragma unroll
            for (int t = 0; t < 2; t++) {
                LDSM4(bh[t], bBase + t * (16 * ROWB) + ks * 32);
                LDSM4(bl[t], bBase + F_SPLIT + t * (16 * ROWB) + ks * 32);
            }
            #pragma unroll
            for (int tm = 0; tm < 4; tm++)
                #pragma unroll
                for (int tn = 0; tn < 4; tn++) {
                    float* c = acc[tm][tn];
                    uint32_t b0h = bh[tn >> 1][(tn & 1) * 2];
                    uint32_t b1h = bh[tn >> 1][(tn & 1) * 2 + 1];
                    uint32_t b0l = bl[tn >> 1][(tn & 1) * 2];
                    uint32_t b1l = bl[tn >> 1][(tn & 1) * 2 + 1];
                    MMA16816(c, w[tm], b0h, b1h);   // w * f_hi
                    MMA16816(c, w[tm], b0l, b1l);   // w * f_lo
                }
        }
    }

    // ---- epilogue: fragment -> out[b][co][y][x] ----
    const int g  = l >> 2;
    const int nc = 2 * (l & 3);
    #pragma unroll
    for (int tm = 0; tm < 4; tm++) {
        #pragma unroll
        for (int tn = 0; tn < 4; tn++) {
            int p = (nw * 32) + tn * 8 + nc;          // pixel index in CTA (0..127)
            int y = y0 + (p >> 6);
            int x = p & 63;
            int co = M0 + tm * 16 + g;
            float* o0 = out + (((size_t)b * COUT + co) * HH + y) * WW + x;
            *(float2*)o0 = make_float2(acc[tm][tn][0], acc[tm][tn][1]);
            float* o1 = o0 + 8 * (size_t)(HH * WW);   // co + 8
            *(float2*)o1 = make_float2(acc[tm][tn][2], acc[tm][tn][3]);
        }
    }
}

// ============================ launch ============================

extern "C" void kernel_launch(void* const* d_in, const int* in_sizes, int n_in,
                              void* d_out, int out_size)
{
    const float* feat = (const float*)d_in[0];   // (16,128,64,64)
    const float* wt   = (const float*)d_in[1];   // (16,128,128,3,3)
    float* out        = (float*)d_out;           // (16,128,64,64)
    (void)in_sizes; (void)n_in; (void)out_size;

    cudaFuncSetAttribute(dynconv_mma_kernel,
                         cudaFuncAttributeMaxDynamicSharedMemorySize, SMEM_TOTAL);

    fsplit_kernel<<<dim3(PADW, BATCH), 512>>>(feat);
    wsplit_kernel<<<(BATCH * COUT * CIN + 255) / 256, 256>>>(wt);
    dynconv_mma_kernel<<<dim3(HH / 2, BATCH), 256, SMEM_TOTAL>>>(out);
}